// round 1
// baseline (speedup 1.0000x reference)
#include <cuda_runtime.h>

#define B_ 32
#define T_ 4096
#define D_ 64
#define S_ 64
#define H_ 128
#define EPSV 1e-10f

// ---------------- scratch (static device globals; no allocation) ----------------
__device__ __align__(16) float g_e[B_ * T_ * S_];      // emission probs (linear)
__device__ __align__(16) float g_alpha[B_ * T_ * S_];  // scaled forward messages
__device__ __align__(16) float g_beta[B_ * T_ * S_];   // scaled backward messages
__device__ __align__(16) float g_M[S_ * S_];           // trans_probs + EPS (linear)
__device__ __align__(16) float g_pi[S_];               // softmax(log_init_probs)
__device__ __align__(16) float g_margpart[B_ * 16 * S_];

typedef unsigned long long u64;

// ---------------- packed f32x2 helpers (sm_100+) ----------------
__device__ __forceinline__ u64 pack2(float x, float y) {
    u64 r; asm("mov.b64 %0, {%1, %2};" : "=l"(r) : "f"(x), "f"(y)); return r;
}
__device__ __forceinline__ void unpack2(u64 v, float& x, float& y) {
    asm("mov.b64 {%0, %1}, %2;" : "=f"(x), "=f"(y) : "l"(v));
}
__device__ __forceinline__ u64 fma2(u64 a, u64 b, u64 c) {
    u64 d; asm("fma.rn.f32x2 %0, %1, %2, %3;" : "=l"(d) : "l"(a), "l"(b), "l"(c)); return d;
}
__device__ __forceinline__ u64 add2(u64 a, u64 b) {
    u64 d; asm("add.rn.f32x2 %0, %1, %2;" : "=l"(d) : "l"(a), "l"(b)); return d;
}

// ---------------- setup: transition softmax, init probs, durations ----------------
__global__ void setup_kernel(const float* __restrict__ ltm, const float* __restrict__ lip,
                             const float* __restrict__ lr, const float* __restrict__ lp,
                             float* __restrict__ out_dur) {
    int j = threadIdx.x;  // 0..63, handles row j of transition matrix
    float row[S_];
    float m = -1e30f;
#pragma unroll
    for (int k = 0; k < S_; k++) {
        float v = (k == j) ? -1e10f : ltm[j * S_ + k];
        row[k] = v;
        m = fmaxf(m, v);
    }
    float s = 0.f;
#pragma unroll
    for (int k = 0; k < S_; k++) { row[k] = expf(row[k] - m); s += row[k]; }
    float inv = 1.f / s;
#pragma unroll
    for (int k = 0; k < S_; k++) g_M[j * S_ + k] = row[k] * inv + EPSV;

    // pi = softmax(log_init_probs)  (redundant per-thread, one-time)
    float m2 = -1e30f;
#pragma unroll
    for (int k = 0; k < S_; k++) m2 = fmaxf(m2, lip[k]);
    float s2 = 0.f;
#pragma unroll
    for (int k = 0; k < S_; k++) s2 += expf(lip[k] - m2);
    g_pi[j] = expf(lip[j] - m2) / s2;

    // expected durations
    float r = expf(lr[j]);
    float p = 1.f / (1.f + expf(-lp[j]));
    out_dur[j] = r * (1.f - p) / p;
}

// ---------------- emission MLP + softmax ----------------
// One warp computes one (b,t) row. Weights staged in dynamic SMEM (~129 KB).
// Lane l owns hidden units 4l..4l+3 (layers 1,2) and outputs 2l,2l+1 (layer 3).
__global__ void __launch_bounds__(256) mlp_kernel(
    const float* __restrict__ obs,
    const float* __restrict__ W1, const float* __restrict__ b1,
    const float* __restrict__ W2, const float* __restrict__ b2,
    const float* __restrict__ W3, const float* __restrict__ b3) {
    extern __shared__ float sm[];
    float* W1s = sm;                    // 64*128
    float* W2s = W1s + D_ * H_;         // 128*128
    float* W3s = W2s + H_ * H_;         // 128*64
    float* b1s = W3s + H_ * S_;         // 128
    float* b2s = b1s + H_;              // 128
    float* b3s = b2s + H_;              // 64
    int tid = threadIdx.x;
    for (int i = tid; i < D_ * H_; i += 256) W1s[i] = W1[i];
    for (int i = tid; i < H_ * H_; i += 256) W2s[i] = W2[i];
    for (int i = tid; i < H_ * S_; i += 256) W3s[i] = W3[i];
    if (tid < H_) { b1s[tid] = b1[tid]; b2s[tid] = b2[tid]; }
    if (tid < S_) b3s[tid] = b3[tid];
    __syncthreads();

    int w = tid >> 5, l = tid & 31;
    int r0 = blockIdx.x * 256 + w * 32;
    const unsigned FULL = 0xffffffffu;

    for (int k = 0; k < 32; k++) {
        int r = r0 + k;
        const float* xr = obs + (size_t)r * D_;
        float x0 = xr[l], x1 = xr[32 + l];

        // ---- layer 1: (64 -> 128), lane outputs h = 4l..4l+3
        u64 a0 = *(const u64*)&b1s[4 * l];
        u64 a1 = *(const u64*)&b1s[4 * l + 2];
#pragma unroll
        for (int o = 0; o < 32; o++) {
            float v0 = __shfl_sync(FULL, x0, o);
            float v1 = __shfl_sync(FULL, x1, o);
            u64 p0 = pack2(v0, v0), p1 = pack2(v1, v1);
            ulonglong2 q0 = *(const ulonglong2*)&W1s[o * H_ + 4 * l];
            ulonglong2 q1 = *(const ulonglong2*)&W1s[(o + 32) * H_ + 4 * l];
            a0 = fma2(p0, q0.x, a0); a1 = fma2(p0, q0.y, a1);
            a0 = fma2(p1, q1.x, a0); a1 = fma2(p1, q1.y, a1);
        }
        float h1v[4];
        unpack2(a0, h1v[0], h1v[1]); unpack2(a1, h1v[2], h1v[3]);
#pragma unroll
        for (int q = 0; q < 4; q++) h1v[q] = fmaxf(h1v[q], 0.f);

        // ---- layer 2: (128 -> 128)
        u64 c0 = *(const u64*)&b2s[4 * l];
        u64 c1 = *(const u64*)&b2s[4 * l + 2];
#pragma unroll
        for (int o = 0; o < 32; o++) {
#pragma unroll
            for (int q = 0; q < 4; q++) {
                float v = __shfl_sync(FULL, h1v[q], o);
                u64 pv = pack2(v, v);
                ulonglong2 q2 = *(const ulonglong2*)&W2s[(o * 4 + q) * H_ + 4 * l];
                c0 = fma2(pv, q2.x, c0); c1 = fma2(pv, q2.y, c1);
            }
        }
        float h2v[4];
        unpack2(c0, h2v[0], h2v[1]); unpack2(c1, h2v[2], h2v[3]);
#pragma unroll
        for (int q = 0; q < 4; q++) h2v[q] = fmaxf(h2v[q], 0.f);

        // ---- layer 3: (128 -> 64), lane outputs 2l, 2l+1
        u64 e0 = *(const u64*)&b3s[2 * l];
#pragma unroll
        for (int o = 0; o < 32; o++) {
#pragma unroll
            for (int q = 0; q < 4; q++) {
                float v = __shfl_sync(FULL, h2v[q], o);
                u64 pv = pack2(v, v);
                u64 w3 = *(const u64*)&W3s[(o * 4 + q) * S_ + 2 * l];
                e0 = fma2(pv, w3, e0);
            }
        }
        float z0, z1;
        unpack2(e0, z0, z1);

        // ---- softmax over the 64 logits held across the warp (2 per lane)
        float mx = fmaxf(z0, z1);
#pragma unroll
        for (int off = 16; off; off >>= 1) mx = fmaxf(mx, __shfl_xor_sync(FULL, mx, off));
        float ex = __expf(z0 - mx), ey = __expf(z1 - mx);
        float s = ex + ey;
#pragma unroll
        for (int off = 16; off; off >>= 1) s += __shfl_xor_sync(FULL, s, off);
        float inv = __fdividef(1.f, s);
        *(float2*)&g_e[(size_t)r * S_ + 2 * l] = make_float2(ex * inv, ey * inv);
    }
}

// ---------------- scaled forward/backward recursions ----------------
// blocks 0..31: forward for batch b; blocks 32..63: backward for batch b.
// Thread j holds column j (fwd) / row j (bwd) of M as 32 packed f32x2 registers.
// Vector ping-pongs through SMEM; per-step scale = 1/sum(prev vector);
// all per-(b,t) scales cancel in gamma; LL[b] = sum_t log(sum_j v_t).
__global__ void __launch_bounds__(64) recursion_kernel(float* __restrict__ out_ll) {
    __shared__ __align__(16) float sv[2][S_];
    int j = threadIdx.x;
    int b = blockIdx.x & 31;
    bool isbwd = blockIdx.x >= 32;

    u64 Mp[32];
    if (!isbwd) {
#pragma unroll
        for (int k = 0; k < 32; k++)
            Mp[k] = pack2(g_M[(2 * k) * S_ + j], g_M[(2 * k + 1) * S_ + j]);
    } else {
#pragma unroll
        for (int k = 0; k < 32; k++)
            Mp[k] = *(const u64*)&g_M[j * S_ + 2 * k];
    }
    const float* eb = g_e + (size_t)b * T_ * S_;

    if (!isbwd) {
        float* ab = g_alpha + (size_t)b * T_ * S_;
        float a0 = g_pi[j] * eb[j];  // t=0 uses raw emission (no EPS), matching ref
        sv[0][j] = a0;
        ab[j] = a0;
        double llacc = 0.0;
        float en1 = eb[S_ + j] + EPSV;
        float en2 = eb[2 * S_ + j] + EPSV;
        __syncthreads();
        int p = 0;
        for (int t = 1; t < T_; t++) {
            const ulonglong2* v4 = (const ulonglong2*)sv[p];
            u64 acc0 = 0, acc1 = 0, acc2 = 0, acc3 = 0, s0 = 0, s1 = 0;
#pragma unroll
            for (int n = 0; n < 16; n += 2) {
                ulonglong2 qa = v4[n], qb = v4[n + 1];
                acc0 = fma2(qa.x, Mp[2 * n], acc0);
                acc1 = fma2(qa.y, Mp[2 * n + 1], acc1);
                acc2 = fma2(qb.x, Mp[2 * n + 2], acc2);
                acc3 = fma2(qb.y, Mp[2 * n + 3], acc3);
                s0 = add2(s0, add2(qa.x, qa.y));
                s1 = add2(s1, add2(qb.x, qb.y));
            }
            u64 at = add2(add2(acc0, acc1), add2(acc2, acc3));
            u64 st = add2(s0, s1);
            float tx, ty, sx, sy;
            unpack2(at, tx, ty);
            unpack2(st, sx, sy);
            float csum = sx + sy;                      // = sum of v_{t-1}
            float a = __fdividef((tx + ty) * en1, csum);
            llacc += (double)__logf(csum);
            sv[1 - p][j] = a;
            ab[(size_t)t * S_ + j] = a;
            en1 = en2;
            if (t + 2 < T_) en2 = eb[(size_t)(t + 2) * S_ + j] + EPSV;
            __syncthreads();
            p ^= 1;
        }
        float fs = 0.f;
#pragma unroll
        for (int k = 0; k < S_; k++) fs += sv[p][k];
        llacc += (double)__logf(fs);
        if (j == 0) out_ll[b] = (float)llacc;
    } else {
        float* bb = g_beta + (size_t)b * T_ * S_;
        bb[(size_t)(T_ - 1) * S_ + j] = 1.f;
        sv[0][j] = eb[(size_t)(T_ - 1) * S_ + j] + EPSV;  // u_{T-1} = e~_{T-1} * 1
        float en1 = eb[(size_t)(T_ - 2) * S_ + j] + EPSV;
        float en2 = eb[(size_t)(T_ - 3) * S_ + j] + EPSV;
        __syncthreads();
        int p = 0;
        for (int t = T_ - 2; t >= 0; t--) {
            const ulonglong2* v4 = (const ulonglong2*)sv[p];
            u64 acc0 = 0, acc1 = 0, acc2 = 0, acc3 = 0, s0 = 0, s1 = 0;
#pragma unroll
            for (int n = 0; n < 16; n += 2) {
                ulonglong2 qa = v4[n], qb = v4[n + 1];
                acc0 = fma2(qa.x, Mp[2 * n], acc0);
                acc1 = fma2(qa.y, Mp[2 * n + 1], acc1);
                acc2 = fma2(qb.x, Mp[2 * n + 2], acc2);
                acc3 = fma2(qb.y, Mp[2 * n + 3], acc3);
                s0 = add2(s0, add2(qa.x, qa.y));
                s1 = add2(s1, add2(qb.x, qb.y));
            }
            u64 at = add2(add2(acc0, acc1), add2(acc2, acc3));
            u64 st = add2(s0, s1);
            float tx, ty, sx, sy;
            unpack2(at, tx, ty);
            unpack2(st, sx, sy);
            float csum = sx + sy;
            float bt = __fdividef(tx + ty, csum);
            bb[(size_t)t * S_ + j] = bt;
            sv[1 - p][j] = bt * en1;  // u_t = beta_t * e~_t (for next step)
            en1 = en2;
            if (t >= 2) en2 = eb[(size_t)(t - 2) * S_ + j] + EPSV;
            __syncthreads();
            p ^= 1;
        }
    }
}

// ---------------- gamma: normalized posteriors + marginal partials ----------------
__global__ void __launch_bounds__(256) gamma_kernel(float* __restrict__ out_probs) {
    int b = blockIdx.x >> 4, chunk = blockIdx.x & 15;
    int w = threadIdx.x >> 5, l = threadIdx.x & 31;
    __shared__ float smarg[8][S_];
    const unsigned FULL = 0xffffffffu;
    float mx = 0.f, my = 0.f;
    int tbase = chunk * 256 + w;
    size_t base = (size_t)b * T_ * S_;
#pragma unroll 4
    for (int k = 0; k < 32; k++) {
        int t = tbase + k * 8;
        size_t idx = base + (size_t)t * S_ + 2 * l;
        float2 va = *(const float2*)&g_alpha[idx];
        float2 vb = *(const float2*)&g_beta[idx];
        float px = va.x * vb.x, py = va.y * vb.y;
        float s = px + py;
#pragma unroll
        for (int off = 16; off; off >>= 1) s += __shfl_xor_sync(FULL, s, off);
        float inv = __fdividef(1.f, s);
        px *= inv; py *= inv;
        *(float2*)&out_probs[idx] = make_float2(px, py);
        mx += px; my += py;
    }
    smarg[w][2 * l] = mx;
    smarg[w][2 * l + 1] = my;
    __syncthreads();
    if (threadIdx.x < S_) {
        float s = 0.f;
#pragma unroll
        for (int ww = 0; ww < 8; ww++) s += smarg[ww][threadIdx.x];
        g_margpart[(size_t)blockIdx.x * S_ + threadIdx.x] = s;
    }
}

__global__ void margreduce_kernel(float* __restrict__ out_marg) {
    int i = blockIdx.x * blockDim.x + threadIdx.x;  // 0..2047
    int b = i >> 6, j = i & 63;
    float s = 0.f;
#pragma unroll
    for (int c = 0; c < 16; c++) s += g_margpart[(size_t)(b * 16 + c) * S_ + j];
    out_marg[i] = s * (1.f / (float)T_);
}

// ---------------- launch ----------------
extern "C" void kernel_launch(void* const* d_in, const int* in_sizes, int n_in,
                              void* d_out, int out_size) {
    const float* obs = (const float*)d_in[0];
    const float* W1 = (const float*)d_in[1];
    const float* b1 = (const float*)d_in[2];
    const float* W2 = (const float*)d_in[3];
    const float* b2 = (const float*)d_in[4];
    const float* W3 = (const float*)d_in[5];
    const float* b3 = (const float*)d_in[6];
    const float* ltm = (const float*)d_in[7];
    const float* lip = (const float*)d_in[8];
    const float* lr = (const float*)d_in[9];
    const float* lp = (const float*)d_in[10];

    float* out = (float*)d_out;
    float* out_probs = out;                                   // B*T*S
    float* out_marg = out + (size_t)B_ * T_ * S_;             // B*S
    float* out_dur = out_marg + (size_t)B_ * S_;              // S
    float* out_ll = out_dur + S_;                             // B

    const int smem_bytes = (D_ * H_ + H_ * H_ + H_ * S_ + H_ + H_ + S_) * 4;  // 132352
    cudaFuncSetAttribute(mlp_kernel, cudaFuncAttributeMaxDynamicSharedMemorySize, smem_bytes);

    setup_kernel<<<1, 64>>>(ltm, lip, lr, lp, out_dur);
    mlp_kernel<<<512, 256, smem_bytes>>>(obs, W1, b1, W2, b2, W3, b3);
    recursion_kernel<<<64, 64>>>(out_ll);
    gamma_kernel<<<512, 256>>>(out_probs);
    margreduce_kernel<<<8, 256>>>(out_marg);
}

// round 2
// speedup vs baseline: 1.3100x; 1.3100x over previous
#include <cuda_runtime.h>

#define B_ 32
#define T_ 4096
#define D_ 64
#define S_ 64
#define H_ 128
#define EPSV 1e-10f

// ---------------- scratch (static device globals; no allocation) ----------------
__device__ __align__(16) float g_e[B_ * T_ * S_];      // emission probs (linear)
__device__ __align__(16) float g_alpha[B_ * T_ * S_];  // scaled forward messages
__device__ __align__(16) float g_beta[B_ * T_ * S_];   // scaled backward messages
__device__ __align__(16) float g_M[S_ * S_];           // trans_probs + EPS (linear)
__device__ __align__(16) float g_pi[S_];               // softmax(log_init_probs)
__device__ __align__(16) float g_margpart[B_ * 16 * S_];

typedef unsigned long long u64;

// ---------------- packed f32x2 helpers (sm_100+) ----------------
__device__ __forceinline__ u64 pack2(float x, float y) {
    u64 r; asm("mov.b64 %0, {%1, %2};" : "=l"(r) : "f"(x), "f"(y)); return r;
}
__device__ __forceinline__ void unpack2(u64 v, float& x, float& y) {
    asm("mov.b64 {%0, %1}, %2;" : "=f"(x), "=f"(y) : "l"(v));
}
__device__ __forceinline__ u64 fma2(u64 a, u64 b, u64 c) {
    u64 d; asm("fma.rn.f32x2 %0, %1, %2, %3;" : "=l"(d) : "l"(a), "l"(b), "l"(c)); return d;
}
__device__ __forceinline__ u64 add2(u64 a, u64 b) {
    u64 d; asm("add.rn.f32x2 %0, %1, %2;" : "=l"(d) : "l"(a), "l"(b)); return d;
}

// ---------------- setup: transition softmax, init probs, durations ----------------
__global__ void setup_kernel(const float* __restrict__ ltm, const float* __restrict__ lip,
                             const float* __restrict__ lr, const float* __restrict__ lp,
                             float* __restrict__ out_dur) {
    int j = threadIdx.x;  // 0..63, handles row j of transition matrix
    float row[S_];
    float m = -1e30f;
#pragma unroll
    for (int k = 0; k < S_; k++) {
        float v = (k == j) ? -1e10f : ltm[j * S_ + k];
        row[k] = v;
        m = fmaxf(m, v);
    }
    float s = 0.f;
#pragma unroll
    for (int k = 0; k < S_; k++) { row[k] = expf(row[k] - m); s += row[k]; }
    float inv = 1.f / s;
#pragma unroll
    for (int k = 0; k < S_; k++) g_M[j * S_ + k] = row[k] * inv + EPSV;

    float m2 = -1e30f;
#pragma unroll
    for (int k = 0; k < S_; k++) m2 = fmaxf(m2, lip[k]);
    float s2 = 0.f;
#pragma unroll
    for (int k = 0; k < S_; k++) s2 += expf(lip[k] - m2);
    g_pi[j] = expf(lip[j] - m2) / s2;

    float r = expf(lr[j]);
    float p = 1.f / (1.f + expf(-lp[j]));
    out_dur[j] = r * (1.f - p) / p;
}

// ---------------- emission MLP + softmax ----------------
// 128 threads = 4 warps per block; each warp processes 32 rows in 4 groups of 8.
// Weights staged in SMEM; activations written DUPLICATED ((v,v) pairs) to a
// per-warp smem buffer so broadcast LDS.128 feeds fma.rn.f32x2 directly
// (no shuffles, no pack MOVs on the hot path). Weight smem traffic is
// amortized over 8 rows per load.
__global__ void __launch_bounds__(128) mlp_kernel(
    const float* __restrict__ obs,
    const float* __restrict__ W1, const float* __restrict__ b1,
    const float* __restrict__ W2, const float* __restrict__ b2,
    const float* __restrict__ W3, const float* __restrict__ b3) {
    extern __shared__ float sm[];
    float* W1s = sm;                    // 64*128   = 8192
    float* W2s = W1s + D_ * H_;         // 128*128  = 16384
    float* W3s = W2s + H_ * H_;         // 128*64   = 8192
    float* b1s = W3s + H_ * S_;         // 128
    float* b2s = b1s + H_;              // 128
    float* b3s = b2s + H_;              // 64
    float* bufs = b3s + S_;             // 4 warps * 4096 floats

    int tid = threadIdx.x;
    for (int i = tid; i < (D_ * H_) / 4; i += 128)
        ((float4*)W1s)[i] = ((const float4*)W1)[i];
    for (int i = tid; i < (H_ * H_) / 4; i += 128)
        ((float4*)W2s)[i] = ((const float4*)W2)[i];
    for (int i = tid; i < (H_ * S_) / 4; i += 128)
        ((float4*)W3s)[i] = ((const float4*)W3)[i];
    if (tid < H_) { b1s[tid] = b1[tid]; b2s[tid] = b2[tid]; }
    if (tid < S_) b3s[tid] = b3[tid];
    __syncthreads();

    int w = tid >> 5, l = tid & 31;
    float* bufA = bufs + w * 4096;       // 2048 floats (x dup / h2 dup)
    float* bufB = bufA + 2048;           // 2048 floats (h1 dup)
    const unsigned FULL = 0xffffffffu;

    int rowbase = blockIdx.x * 128 + w * 32;

    for (int g = 0; g < 4; g++) {
        int r0 = rowbase + g * 8;
        __syncwarp();
        // ---- stage x duplicated: bufA[rr*128 + 2*v .. ] = (x_v, x_v)
#pragma unroll
        for (int rr = 0; rr < 8; rr++) {
            float2 xv = *(const float2*)&obs[(size_t)(r0 + rr) * D_ + 2 * l];
            *(float4*)&bufA[rr * 128 + 4 * l] = make_float4(xv.x, xv.x, xv.y, xv.y);
        }
        __syncwarp();

        // ---- layer 1: (64 -> 128). Lane owns output cols 4l..4l+3.
        u64 acc[8][2];
        {
            u64 bias0 = *(const u64*)&b1s[4 * l];
            u64 bias1 = *(const u64*)&b1s[4 * l + 2];
#pragma unroll
            for (int rr = 0; rr < 8; rr++) { acc[rr][0] = bias0; acc[rr][1] = bias1; }
        }
#pragma unroll 4
        for (int kp = 0; kp < 32; kp++) {
            ulonglong2 w0 = *(const ulonglong2*)&W1s[(2 * kp) * H_ + 4 * l];
            ulonglong2 w1 = *(const ulonglong2*)&W1s[(2 * kp + 1) * H_ + 4 * l];
#pragma unroll
            for (int rr = 0; rr < 8; rr++) {
                ulonglong2 xq = *(const ulonglong2*)&bufA[rr * 128 + 4 * kp];
                acc[rr][0] = fma2(xq.x, w0.x, acc[rr][0]);
                acc[rr][1] = fma2(xq.x, w0.y, acc[rr][1]);
                acc[rr][0] = fma2(xq.y, w1.x, acc[rr][0]);
                acc[rr][1] = fma2(xq.y, w1.y, acc[rr][1]);
            }
        }
        // relu + write h1 duplicated to bufB (value v at float offset 2v)
#pragma unroll
        for (int rr = 0; rr < 8; rr++) {
            float h0, h1v, h2v, h3;
            unpack2(acc[rr][0], h0, h1v);
            unpack2(acc[rr][1], h2v, h3);
            h0 = fmaxf(h0, 0.f); h1v = fmaxf(h1v, 0.f);
            h2v = fmaxf(h2v, 0.f); h3 = fmaxf(h3, 0.f);
            *(float4*)&bufB[rr * 256 + 8 * l] = make_float4(h0, h0, h1v, h1v);
            *(float4*)&bufB[rr * 256 + 8 * l + 4] = make_float4(h2v, h2v, h3, h3);
        }
        __syncwarp();

        // ---- layer 2: (128 -> 128)
        {
            u64 bias0 = *(const u64*)&b2s[4 * l];
            u64 bias1 = *(const u64*)&b2s[4 * l + 2];
#pragma unroll
            for (int rr = 0; rr < 8; rr++) { acc[rr][0] = bias0; acc[rr][1] = bias1; }
        }
#pragma unroll 4
        for (int kp = 0; kp < 64; kp++) {
            ulonglong2 w0 = *(const ulonglong2*)&W2s[(2 * kp) * H_ + 4 * l];
            ulonglong2 w1 = *(const ulonglong2*)&W2s[(2 * kp + 1) * H_ + 4 * l];
#pragma unroll
            for (int rr = 0; rr < 8; rr++) {
                ulonglong2 xq = *(const ulonglong2*)&bufB[rr * 256 + 4 * kp];
                acc[rr][0] = fma2(xq.x, w0.x, acc[rr][0]);
                acc[rr][1] = fma2(xq.x, w0.y, acc[rr][1]);
                acc[rr][0] = fma2(xq.y, w1.x, acc[rr][0]);
                acc[rr][1] = fma2(xq.y, w1.y, acc[rr][1]);
            }
        }
        // relu + write h2 duplicated to bufA (x no longer needed)
#pragma unroll
        for (int rr = 0; rr < 8; rr++) {
            float h0, h1v, h2v, h3;
            unpack2(acc[rr][0], h0, h1v);
            unpack2(acc[rr][1], h2v, h3);
            h0 = fmaxf(h0, 0.f); h1v = fmaxf(h1v, 0.f);
            h2v = fmaxf(h2v, 0.f); h3 = fmaxf(h3, 0.f);
            *(float4*)&bufA[rr * 256 + 8 * l] = make_float4(h0, h0, h1v, h1v);
            *(float4*)&bufA[rr * 256 + 8 * l + 4] = make_float4(h2v, h2v, h3, h3);
        }
        __syncwarp();

        // ---- layer 3: (128 -> 64). Lane owns output cols 2l, 2l+1.
        u64 acc3[8];
        {
            u64 bias = *(const u64*)&b3s[2 * l];
#pragma unroll
            for (int rr = 0; rr < 8; rr++) acc3[rr] = bias;
        }
#pragma unroll 4
        for (int kp = 0; kp < 64; kp++) {
            u64 w0 = *(const u64*)&W3s[(2 * kp) * S_ + 2 * l];
            u64 w1 = *(const u64*)&W3s[(2 * kp + 1) * S_ + 2 * l];
#pragma unroll
            for (int rr = 0; rr < 8; rr++) {
                ulonglong2 xq = *(const ulonglong2*)&bufA[rr * 256 + 4 * kp];
                acc3[rr] = fma2(xq.x, w0, acc3[rr]);
                acc3[rr] = fma2(xq.y, w1, acc3[rr]);
            }
        }

        // ---- softmax over the 64 logits held across the warp (2 per lane)
#pragma unroll
        for (int rr = 0; rr < 8; rr++) {
            float z0, z1;
            unpack2(acc3[rr], z0, z1);
            float mx = fmaxf(z0, z1);
#pragma unroll
            for (int off = 16; off; off >>= 1) mx = fmaxf(mx, __shfl_xor_sync(FULL, mx, off));
            float ex = __expf(z0 - mx), ey = __expf(z1 - mx);
            float s = ex + ey;
#pragma unroll
            for (int off = 16; off; off >>= 1) s += __shfl_xor_sync(FULL, s, off);
            float inv = __fdividef(1.f, s);
            *(float2*)&g_e[(size_t)(r0 + rr) * S_ + 2 * l] = make_float2(ex * inv, ey * inv);
        }
    }
}

// ---------------- scaled forward/backward recursions ----------------
// blocks 0..31: forward for batch b; blocks 32..63: backward for batch b.
// Thread j holds column j (fwd) / row j (bwd) of M as 32 packed f32x2 registers.
// Vector ping-pongs through SMEM; per-step scale = 1/sum(prev vector).
// Emission values are prefetched 8 steps ahead through a register ring so the
// DRAM/L2 latency of g_e reads never sits on the per-step critical path.
__global__ void __launch_bounds__(64) recursion_kernel(float* __restrict__ out_ll) {
    __shared__ __align__(16) float sv[2][S_];
    int j = threadIdx.x;
    int b = blockIdx.x & 31;
    bool isbwd = blockIdx.x >= 32;

    u64 Mp[32];
    if (!isbwd) {
#pragma unroll
        for (int k = 0; k < 32; k++)
            Mp[k] = pack2(g_M[(2 * k) * S_ + j], g_M[(2 * k + 1) * S_ + j]);
    } else {
#pragma unroll
        for (int k = 0; k < 32; k++)
            Mp[k] = *(const u64*)&g_M[j * S_ + 2 * k];
    }
    const float* eb = g_e + (size_t)b * T_ * S_;

    if (!isbwd) {
        float* ab = g_alpha + (size_t)b * T_ * S_;
        float a0 = g_pi[j] * eb[j];  // t=0 uses raw emission (no EPS), matching ref
        sv[0][j] = a0;
        ab[j] = a0;
        double llacc = 0.0;
        float en[8];
#pragma unroll
        for (int i = 0; i < 8; i++) en[i] = eb[(size_t)(1 + i) * S_ + j] + EPSV;
        __syncthreads();
        int p = 0;
        for (int t0 = 1; t0 < T_; t0 += 8) {
#pragma unroll
            for (int i = 0; i < 8; i++) {
                int t = t0 + i;
                if (t < T_) {
                    const ulonglong2* v4 = (const ulonglong2*)sv[p];
                    u64 acc0 = 0, acc1 = 0, acc2 = 0, acc3 = 0, s0 = 0, s1 = 0;
#pragma unroll
                    for (int n = 0; n < 16; n += 2) {
                        ulonglong2 qa = v4[n], qb = v4[n + 1];
                        acc0 = fma2(qa.x, Mp[2 * n], acc0);
                        acc1 = fma2(qa.y, Mp[2 * n + 1], acc1);
                        acc2 = fma2(qb.x, Mp[2 * n + 2], acc2);
                        acc3 = fma2(qb.y, Mp[2 * n + 3], acc3);
                        s0 = add2(s0, add2(qa.x, qa.y));
                        s1 = add2(s1, add2(qb.x, qb.y));
                    }
                    u64 at = add2(add2(acc0, acc1), add2(acc2, acc3));
                    u64 st = add2(s0, s1);
                    float tx, ty, sx, sy;
                    unpack2(at, tx, ty);
                    unpack2(st, sx, sy);
                    float csum = sx + sy;  // = sum of v_{t-1}
                    float a = __fdividef((tx + ty) * en[i], csum);
                    llacc += (double)__logf(csum);
                    sv[1 - p][j] = a;
                    ab[(size_t)t * S_ + j] = a;
                    if (t + 8 < T_) en[i] = eb[(size_t)(t + 8) * S_ + j] + EPSV;
                    __syncthreads();
                    p ^= 1;
                }
            }
        }
        float fs = 0.f;
#pragma unroll
        for (int k = 0; k < S_; k++) fs += sv[p][k];
        llacc += (double)__logf(fs);
        if (j == 0) out_ll[b] = (float)llacc;
    } else {
        float* bb = g_beta + (size_t)b * T_ * S_;
        bb[(size_t)(T_ - 1) * S_ + j] = 1.f;
        sv[0][j] = eb[(size_t)(T_ - 1) * S_ + j] + EPSV;  // u_{T-1} = e~_{T-1} * 1
        float en[8];
#pragma unroll
        for (int i = 0; i < 8; i++) en[i] = eb[(size_t)(T_ - 2 - i) * S_ + j] + EPSV;
        __syncthreads();
        int p = 0;
        for (int t0 = T_ - 2; t0 >= 0; t0 -= 8) {
#pragma unroll
            for (int i = 0; i < 8; i++) {
                int t = t0 - i;
                if (t >= 0) {
                    const ulonglong2* v4 = (const ulonglong2*)sv[p];
                    u64 acc0 = 0, acc1 = 0, acc2 = 0, acc3 = 0, s0 = 0, s1 = 0;
#pragma unroll
                    for (int n = 0; n < 16; n += 2) {
                        ulonglong2 qa = v4[n], qb = v4[n + 1];
                        acc0 = fma2(qa.x, Mp[2 * n], acc0);
                        acc1 = fma2(qa.y, Mp[2 * n + 1], acc1);
                        acc2 = fma2(qb.x, Mp[2 * n + 2], acc2);
                        acc3 = fma2(qb.y, Mp[2 * n + 3], acc3);
                        s0 = add2(s0, add2(qa.x, qa.y));
                        s1 = add2(s1, add2(qb.x, qb.y));
                    }
                    u64 at = add2(add2(acc0, acc1), add2(acc2, acc3));
                    u64 st = add2(s0, s1);
                    float tx, ty, sx, sy;
                    unpack2(at, tx, ty);
                    unpack2(st, sx, sy);
                    float csum = sx + sy;
                    float bt = __fdividef(tx + ty, csum);
                    bb[(size_t)t * S_ + j] = bt;
                    sv[1 - p][j] = bt * en[i];  // u_t = beta_t * e~_t (for next step)
                    if (t - 8 >= 0) en[i] = eb[(size_t)(t - 8) * S_ + j] + EPSV;
                    __syncthreads();
                    p ^= 1;
                }
            }
        }
    }
}

// ---------------- gamma: normalized posteriors + marginal partials ----------------
__global__ void __launch_bounds__(256) gamma_kernel(float* __restrict__ out_probs) {
    int b = blockIdx.x >> 4, chunk = blockIdx.x & 15;
    int w = threadIdx.x >> 5, l = threadIdx.x & 31;
    __shared__ float smarg[8][S_];
    const unsigned FULL = 0xffffffffu;
    float mx = 0.f, my = 0.f;
    int tbase = chunk * 256 + w;
    size_t base = (size_t)b * T_ * S_;
#pragma unroll 4
    for (int k = 0; k < 32; k++) {
        int t = tbase + k * 8;
        size_t idx = base + (size_t)t * S_ + 2 * l;
        float2 va = *(const float2*)&g_alpha[idx];
        float2 vb = *(const float2*)&g_beta[idx];
        float px = va.x * vb.x, py = va.y * vb.y;
        float s = px + py;
#pragma unroll
        for (int off = 16; off; off >>= 1) s += __shfl_xor_sync(FULL, s, off);
        float inv = __fdividef(1.f, s);
        px *= inv; py *= inv;
        *(float2*)&out_probs[idx] = make_float2(px, py);
        mx += px; my += py;
    }
    smarg[w][2 * l] = mx;
    smarg[w][2 * l + 1] = my;
    __syncthreads();
    if (threadIdx.x < S_) {
        float s = 0.f;
#pragma unroll
        for (int ww = 0; ww < 8; ww++) s += smarg[ww][threadIdx.x];
        g_margpart[(size_t)blockIdx.x * S_ + threadIdx.x] = s;
    }
}

__global__ void margreduce_kernel(float* __restrict__ out_marg) {
    int i = blockIdx.x * blockDim.x + threadIdx.x;  // 0..2047
    int b = i >> 6, j = i & 63;
    float s = 0.f;
#pragma unroll
    for (int c = 0; c < 16; c++) s += g_margpart[(size_t)(b * 16 + c) * S_ + j];
    out_marg[i] = s * (1.f / (float)T_);
}

// ---------------- launch ----------------
extern "C" void kernel_launch(void* const* d_in, const int* in_sizes, int n_in,
                              void* d_out, int out_size) {
    const float* obs = (const float*)d_in[0];
    const float* W1 = (const float*)d_in[1];
    const float* b1 = (const float*)d_in[2];
    const float* W2 = (const float*)d_in[3];
    const float* b2 = (const float*)d_in[4];
    const float* W3 = (const float*)d_in[5];
    const float* b3 = (const float*)d_in[6];
    const float* ltm = (const float*)d_in[7];
    const float* lip = (const float*)d_in[8];
    const float* lr = (const float*)d_in[9];
    const float* lp = (const float*)d_in[10];

    float* out = (float*)d_out;
    float* out_probs = out;                                   // B*T*S
    float* out_marg = out + (size_t)B_ * T_ * S_;             // B*S
    float* out_dur = out_marg + (size_t)B_ * S_;              // S
    float* out_ll = out_dur + S_;                             // B

    // weights + biases + 4 warps * 4096 floats of dup buffers
    const int smem_bytes = (D_ * H_ + H_ * H_ + H_ * S_ + H_ + H_ + S_ + 4 * 4096) * 4;
    cudaFuncSetAttribute(mlp_kernel, cudaFuncAttributeMaxDynamicSharedMemorySize, smem_bytes);

    setup_kernel<<<1, 64>>>(ltm, lip, lr, lp, out_dur);
    mlp_kernel<<<1024, 128, smem_bytes>>>(obs, W1, b1, W2, b2, W3, b3);
    recursion_kernel<<<64, 64>>>(out_ll);
    gamma_kernel<<<512, 256>>>(out_probs);
    margreduce_kernel<<<8, 256>>>(out_marg);
}

// round 3
// speedup vs baseline: 1.5846x; 1.2096x over previous
#include <cuda_runtime.h>

#define B_ 32
#define T_ 4096
#define D_ 64
#define S_ 64
#define H_ 128
#define EPSV 1e-10f

// ---------------- scratch (static device globals; no allocation) ----------------
// g_e padded by 512 floats on each side so the recursion's prefetch ring can
// load unconditionally (branch-free unrolled loop); pad values are never used.
__device__ __align__(16) float g_e_raw[B_ * T_ * S_ + 1024];
__device__ __align__(16) float g_alpha[B_ * T_ * S_];
__device__ __align__(16) float g_beta[B_ * T_ * S_];
__device__ __align__(16) float g_M[S_ * S_];
__device__ __align__(16) float g_pi[S_];
__device__ __align__(16) float g_margpart[B_ * 16 * S_];

typedef unsigned long long u64;

// ---------------- packed f32x2 helpers (sm_100+) ----------------
__device__ __forceinline__ u64 pack2(float x, float y) {
    u64 r; asm("mov.b64 %0, {%1, %2};" : "=l"(r) : "f"(x), "f"(y)); return r;
}
__device__ __forceinline__ void unpack2(u64 v, float& x, float& y) {
    asm("mov.b64 {%0, %1}, %2;" : "=f"(x), "=f"(y) : "l"(v));
}
__device__ __forceinline__ u64 fma2(u64 a, u64 b, u64 c) {
    u64 d; asm("fma.rn.f32x2 %0, %1, %2, %3;" : "=l"(d) : "l"(a), "l"(b), "l"(c)); return d;
}
__device__ __forceinline__ u64 add2(u64 a, u64 b) {
    u64 d; asm("add.rn.f32x2 %0, %1, %2;" : "=l"(d) : "l"(a), "l"(b)); return d;
}

// ---------------- setup: transition softmax, init probs, durations ----------------
__global__ void setup_kernel(const float* __restrict__ ltm, const float* __restrict__ lip,
                             const float* __restrict__ lr, const float* __restrict__ lp,
                             float* __restrict__ out_dur) {
    int j = threadIdx.x;
    float row[S_];
    float m = -1e30f;
#pragma unroll
    for (int k = 0; k < S_; k++) {
        float v = (k == j) ? -1e10f : ltm[j * S_ + k];
        row[k] = v;
        m = fmaxf(m, v);
    }
    float s = 0.f;
#pragma unroll
    for (int k = 0; k < S_; k++) { row[k] = expf(row[k] - m); s += row[k]; }
    float inv = 1.f / s;
#pragma unroll
    for (int k = 0; k < S_; k++) g_M[j * S_ + k] = row[k] * inv + EPSV;

    float m2 = -1e30f;
#pragma unroll
    for (int k = 0; k < S_; k++) m2 = fmaxf(m2, lip[k]);
    float s2 = 0.f;
#pragma unroll
    for (int k = 0; k < S_; k++) s2 += expf(lip[k] - m2);
    g_pi[j] = expf(lip[j] - m2) / s2;

    float r = expf(lr[j]);
    float p = 1.f / (1.f + expf(-lp[j]));
    out_dur[j] = r * (1.f - p) / p;
}

// ---------------- emission MLP + softmax (unchanged from passing R1 kernel) --------
__global__ void __launch_bounds__(128) mlp_kernel(
    const float* __restrict__ obs,
    const float* __restrict__ W1, const float* __restrict__ b1,
    const float* __restrict__ W2, const float* __restrict__ b2,
    const float* __restrict__ W3, const float* __restrict__ b3) {
    extern __shared__ float sm[];
    float* W1s = sm;
    float* W2s = W1s + D_ * H_;
    float* W3s = W2s + H_ * H_;
    float* b1s = W3s + H_ * S_;
    float* b2s = b1s + H_;
    float* b3s = b2s + H_;
    float* bufs = b3s + S_;

    int tid = threadIdx.x;
    for (int i = tid; i < (D_ * H_) / 4; i += 128)
        ((float4*)W1s)[i] = ((const float4*)W1)[i];
    for (int i = tid; i < (H_ * H_) / 4; i += 128)
        ((float4*)W2s)[i] = ((const float4*)W2)[i];
    for (int i = tid; i < (H_ * S_) / 4; i += 128)
        ((float4*)W3s)[i] = ((const float4*)W3)[i];
    if (tid < H_) { b1s[tid] = b1[tid]; b2s[tid] = b2[tid]; }
    if (tid < S_) b3s[tid] = b3[tid];
    __syncthreads();

    int w = tid >> 5, l = tid & 31;
    float* bufA = bufs + w * 4096;
    float* bufB = bufA + 2048;
    const unsigned FULL = 0xffffffffu;
    float* ge = g_e_raw + 512;

    int rowbase = blockIdx.x * 128 + w * 32;

    for (int g = 0; g < 4; g++) {
        int r0 = rowbase + g * 8;
        __syncwarp();
#pragma unroll
        for (int rr = 0; rr < 8; rr++) {
            float2 xv = *(const float2*)&obs[(size_t)(r0 + rr) * D_ + 2 * l];
            *(float4*)&bufA[rr * 128 + 4 * l] = make_float4(xv.x, xv.x, xv.y, xv.y);
        }
        __syncwarp();

        u64 acc[8][2];
        {
            u64 bias0 = *(const u64*)&b1s[4 * l];
            u64 bias1 = *(const u64*)&b1s[4 * l + 2];
#pragma unroll
            for (int rr = 0; rr < 8; rr++) { acc[rr][0] = bias0; acc[rr][1] = bias1; }
        }
#pragma unroll 4
        for (int kp = 0; kp < 32; kp++) {
            ulonglong2 w0 = *(const ulonglong2*)&W1s[(2 * kp) * H_ + 4 * l];
            ulonglong2 w1 = *(const ulonglong2*)&W1s[(2 * kp + 1) * H_ + 4 * l];
#pragma unroll
            for (int rr = 0; rr < 8; rr++) {
                ulonglong2 xq = *(const ulonglong2*)&bufA[rr * 128 + 4 * kp];
                acc[rr][0] = fma2(xq.x, w0.x, acc[rr][0]);
                acc[rr][1] = fma2(xq.x, w0.y, acc[rr][1]);
                acc[rr][0] = fma2(xq.y, w1.x, acc[rr][0]);
                acc[rr][1] = fma2(xq.y, w1.y, acc[rr][1]);
            }
        }
#pragma unroll
        for (int rr = 0; rr < 8; rr++) {
            float h0, h1v, h2v, h3;
            unpack2(acc[rr][0], h0, h1v);
            unpack2(acc[rr][1], h2v, h3);
            h0 = fmaxf(h0, 0.f); h1v = fmaxf(h1v, 0.f);
            h2v = fmaxf(h2v, 0.f); h3 = fmaxf(h3, 0.f);
            *(float4*)&bufB[rr * 256 + 8 * l] = make_float4(h0, h0, h1v, h1v);
            *(float4*)&bufB[rr * 256 + 8 * l + 4] = make_float4(h2v, h2v, h3, h3);
        }
        __syncwarp();

        {
            u64 bias0 = *(const u64*)&b2s[4 * l];
            u64 bias1 = *(const u64*)&b2s[4 * l + 2];
#pragma unroll
            for (int rr = 0; rr < 8; rr++) { acc[rr][0] = bias0; acc[rr][1] = bias1; }
        }
#pragma unroll 4
        for (int kp = 0; kp < 64; kp++) {
            ulonglong2 w0 = *(const ulonglong2*)&W2s[(2 * kp) * H_ + 4 * l];
            ulonglong2 w1 = *(const ulonglong2*)&W2s[(2 * kp + 1) * H_ + 4 * l];
#pragma unroll
            for (int rr = 0; rr < 8; rr++) {
                ulonglong2 xq = *(const ulonglong2*)&bufB[rr * 256 + 4 * kp];
                acc[rr][0] = fma2(xq.x, w0.x, acc[rr][0]);
                acc[rr][1] = fma2(xq.x, w0.y, acc[rr][1]);
                acc[rr][0] = fma2(xq.y, w1.x, acc[rr][0]);
                acc[rr][1] = fma2(xq.y, w1.y, acc[rr][1]);
            }
        }
#pragma unroll
        for (int rr = 0; rr < 8; rr++) {
            float h0, h1v, h2v, h3;
            unpack2(acc[rr][0], h0, h1v);
            unpack2(acc[rr][1], h2v, h3);
            h0 = fmaxf(h0, 0.f); h1v = fmaxf(h1v, 0.f);
            h2v = fmaxf(h2v, 0.f); h3 = fmaxf(h3, 0.f);
            *(float4*)&bufA[rr * 256 + 8 * l] = make_float4(h0, h0, h1v, h1v);
            *(float4*)&bufA[rr * 256 + 8 * l + 4] = make_float4(h2v, h2v, h3, h3);
        }
        __syncwarp();

        u64 acc3[8];
        {
            u64 bias = *(const u64*)&b3s[2 * l];
#pragma unroll
            for (int rr = 0; rr < 8; rr++) acc3[rr] = bias;
        }
#pragma unroll 4
        for (int kp = 0; kp < 64; kp++) {
            u64 w0 = *(const u64*)&W3s[(2 * kp) * S_ + 2 * l];
            u64 w1 = *(const u64*)&W3s[(2 * kp + 1) * S_ + 2 * l];
#pragma unroll
            for (int rr = 0; rr < 8; rr++) {
                ulonglong2 xq = *(const ulonglong2*)&bufA[rr * 256 + 4 * kp];
                acc3[rr] = fma2(xq.x, w0, acc3[rr]);
                acc3[rr] = fma2(xq.y, w1, acc3[rr]);
            }
        }

#pragma unroll
        for (int rr = 0; rr < 8; rr++) {
            float z0, z1;
            unpack2(acc3[rr], z0, z1);
            float mx = fmaxf(z0, z1);
#pragma unroll
            for (int off = 16; off; off >>= 1) mx = fmaxf(mx, __shfl_xor_sync(FULL, mx, off));
            float ex = __expf(z0 - mx), ey = __expf(z1 - mx);
            float s = ex + ey;
#pragma unroll
            for (int off = 16; off; off >>= 1) s += __shfl_xor_sync(FULL, s, off);
            float inv = __fdividef(1.f, s);
            *(float2*)&ge[(size_t)(r0 + rr) * S_ + 2 * l] = make_float2(ex * inv, ey * inv);
        }
    }
}

// ---------------- scaled forward/backward recursions: 1 warp per chain -------------
// 16 blocks x 128 threads; warp w of block handles chain C = blockIdx.x*4 + w.
// Chains 0..31 forward (batch C), 32..63 backward (batch C-32).
// Lane l owns states l and l+32; M column/row pairs live in 128 registers.
// No __syncthreads, no branches in the hot loop (4x unroll, padded prefetch).
// Per-output arithmetic identical to the previously-passing 2-warp version.

#define FSTEP(TT, II, PF)                                                        \
    {                                                                            \
        const ulonglong2* v4 = (const ulonglong2*)svc[p];                        \
        u64 A0 = 0, A1 = 0, A2 = 0, A3 = 0;                                      \
        u64 Bb0 = 0, Bb1 = 0, Bb2 = 0, Bb3 = 0, s0 = 0, s1 = 0;                  \
        _Pragma("unroll")                                                        \
        for (int n = 0; n < 16; n += 2) {                                        \
            ulonglong2 qa = v4[n], qb = v4[n + 1];                               \
            A0 = fma2(qa.x, M0[2 * n], A0);                                      \
            A1 = fma2(qa.y, M0[2 * n + 1], A1);                                  \
            A2 = fma2(qb.x, M0[2 * n + 2], A2);                                  \
            A3 = fma2(qb.y, M0[2 * n + 3], A3);                                  \
            Bb0 = fma2(qa.x, M1[2 * n], Bb0);                                    \
            Bb1 = fma2(qa.y, M1[2 * n + 1], Bb1);                                \
            Bb2 = fma2(qb.x, M1[2 * n + 2], Bb2);                                \
            Bb3 = fma2(qb.y, M1[2 * n + 3], Bb3);                                \
            s0 = add2(s0, add2(qa.x, qa.y));                                     \
            s1 = add2(s1, add2(qb.x, qb.y));                                     \
        }                                                                        \
        u64 atA = add2(add2(A0, A1), add2(A2, A3));                              \
        u64 atB = add2(add2(Bb0, Bb1), add2(Bb2, Bb3));                          \
        u64 st = add2(s0, s1);                                                   \
        float txA, tyA, txB, tyB, sx, sy;                                        \
        unpack2(atA, txA, tyA);                                                  \
        unpack2(atB, txB, tyB);                                                  \
        unpack2(st, sx, sy);                                                     \
        float csum = sx + sy;                                                    \
        float aA = __fdividef((txA + tyA) * enA[II], csum);                      \
        float aB = __fdividef((txB + tyB) * enB[II], csum);                      \
        llacc += (double)__logf(csum);                                           \
        svc[1 - p][l] = aA;                                                      \
        svc[1 - p][l + 32] = aB;                                                 \
        ab[(size_t)(TT)*S_ + l] = aA;                                            \
        ab[(size_t)(TT)*S_ + l + 32] = aB;                                       \
        if (PF) {                                                                \
            enA[II] = eb[(ptrdiff_t)((TT) + 4) * S_ + l] + EPSV;                 \
            enB[II] = eb[(ptrdiff_t)((TT) + 4) * S_ + l + 32] + EPSV;            \
        }                                                                        \
        __syncwarp();                                                            \
        p ^= 1;                                                                  \
    }

#define BSTEP(TT, II, PF)                                                        \
    {                                                                            \
        const ulonglong2* v4 = (const ulonglong2*)svc[p];                        \
        u64 A0 = 0, A1 = 0, A2 = 0, A3 = 0;                                      \
        u64 Bb0 = 0, Bb1 = 0, Bb2 = 0, Bb3 = 0, s0 = 0, s1 = 0;                  \
        _Pragma("unroll")                                                        \
        for (int n = 0; n < 16; n += 2) {                                        \
            ulonglong2 qa = v4[n], qb = v4[n + 1];                               \
            A0 = fma2(qa.x, M0[2 * n], A0);                                      \
            A1 = fma2(qa.y, M0[2 * n + 1], A1);                                  \
            A2 = fma2(qb.x, M0[2 * n + 2], A2);                                  \
            A3 = fma2(qb.y, M0[2 * n + 3], A3);                                  \
            Bb0 = fma2(qa.x, M1[2 * n], Bb0);                                    \
            Bb1 = fma2(qa.y, M1[2 * n + 1], Bb1);                                \
            Bb2 = fma2(qb.x, M1[2 * n + 2], Bb2);                                \
            Bb3 = fma2(qb.y, M1[2 * n + 3], Bb3);                                \
            s0 = add2(s0, add2(qa.x, qa.y));                                     \
            s1 = add2(s1, add2(qb.x, qb.y));                                     \
        }                                                                        \
        u64 atA = add2(add2(A0, A1), add2(A2, A3));                              \
        u64 atB = add2(add2(Bb0, Bb1), add2(Bb2, Bb3));                          \
        u64 st = add2(s0, s1);                                                   \
        float txA, tyA, txB, tyB, sx, sy;                                        \
        unpack2(atA, txA, tyA);                                                  \
        unpack2(atB, txB, tyB);                                                  \
        unpack2(st, sx, sy);                                                     \
        float csum = sx + sy;                                                    \
        float btA = __fdividef(txA + tyA, csum);                                 \
        float btB = __fdividef(txB + tyB, csum);                                 \
        bb[(size_t)(TT)*S_ + l] = btA;                                           \
        bb[(size_t)(TT)*S_ + l + 32] = btB;                                      \
        svc[1 - p][l] = btA * enA[II];                                           \
        svc[1 - p][l + 32] = btB * enB[II];                                      \
        if (PF) {                                                                \
            enA[II] = eb[(ptrdiff_t)((TT)-4) * S_ + l] + EPSV;                   \
            enB[II] = eb[(ptrdiff_t)((TT)-4) * S_ + l + 32] + EPSV;              \
        }                                                                        \
        __syncwarp();                                                            \
        p ^= 1;                                                                  \
    }

__global__ void __launch_bounds__(128, 1) recursion_kernel(float* __restrict__ out_ll) {
    __shared__ __align__(16) float sv[4][2][S_];
    int w = threadIdx.x >> 5, l = threadIdx.x & 31;
    int C = blockIdx.x * 4 + w;
    int b = C & 31;
    bool isbwd = C >= 32;
    float (*svc)[S_] = sv[w];
    const float* eb = g_e_raw + 512 + (size_t)b * T_ * S_;

    u64 M0[32], M1[32];
    if (!isbwd) {
#pragma unroll
        for (int k = 0; k < 32; k++) {
            M0[k] = pack2(g_M[(2 * k) * S_ + l], g_M[(2 * k + 1) * S_ + l]);
            M1[k] = pack2(g_M[(2 * k) * S_ + l + 32], g_M[(2 * k + 1) * S_ + l + 32]);
        }
    } else {
#pragma unroll
        for (int k = 0; k < 32; k++) {
            M0[k] = *(const u64*)&g_M[l * S_ + 2 * k];
            M1[k] = *(const u64*)&g_M[(l + 32) * S_ + 2 * k];
        }
    }

    if (!isbwd) {
        float* ab = g_alpha + (size_t)b * T_ * S_;
        float a0A = g_pi[l] * eb[l];
        float a0B = g_pi[l + 32] * eb[l + 32];
        svc[0][l] = a0A;
        svc[0][l + 32] = a0B;
        ab[l] = a0A;
        ab[l + 32] = a0B;
        double llacc = 0.0;
        float enA[4], enB[4];
#pragma unroll
        for (int i = 0; i < 4; i++) {
            enA[i] = eb[(size_t)(1 + i) * S_ + l] + EPSV;
            enB[i] = eb[(size_t)(1 + i) * S_ + l + 32] + EPSV;
        }
        __syncwarp();
        int p = 0;
        // main: 1023 groups of 4 -> t = 1..4092
        for (int g = 0; g < 1023; g++) {
            int t0 = 1 + 4 * g;
            FSTEP(t0, 0, 1)
            FSTEP(t0 + 1, 1, 1)
            FSTEP(t0 + 2, 2, 1)
            FSTEP(t0 + 3, 3, 1)
        }
        // peel: t = 4093, 4094, 4095 (ring slots 0,1,2; no prefetch)
        FSTEP(T_ - 3, 0, 0)
        FSTEP(T_ - 2, 1, 0)
        FSTEP(T_ - 1, 2, 0)

        float fs = 0.f;
#pragma unroll
        for (int k = 0; k < S_; k++) fs += svc[p][k];
        llacc += (double)__logf(fs);
        if (l == 0) out_ll[b] = (float)llacc;
    } else {
        float* bb = g_beta + (size_t)b * T_ * S_;
        bb[(size_t)(T_ - 1) * S_ + l] = 1.f;
        bb[(size_t)(T_ - 1) * S_ + l + 32] = 1.f;
        svc[0][l] = eb[(size_t)(T_ - 1) * S_ + l] + EPSV;
        svc[0][l + 32] = eb[(size_t)(T_ - 1) * S_ + l + 32] + EPSV;
        double llacc = 0.0;  // unused (keeps macro shared); compiler drops it
        (void)llacc;
        float enA[4], enB[4];
#pragma unroll
        for (int i = 0; i < 4; i++) {
            enA[i] = eb[(size_t)(T_ - 2 - i) * S_ + l] + EPSV;
            enB[i] = eb[(size_t)(T_ - 2 - i) * S_ + l + 32] + EPSV;
        }
        __syncwarp();
        int p = 0;
        // main: 1023 groups of 4 -> t = 4094 down to 3
        for (int g = 0; g < 1023; g++) {
            int t0 = T_ - 2 - 4 * g;
            BSTEP(t0, 0, 1)
            BSTEP(t0 - 1, 1, 1)
            BSTEP(t0 - 2, 2, 1)
            BSTEP(t0 - 3, 3, 1)
        }
        // peel: t = 2, 1, 0 (ring slots 0,1,2; no prefetch)
        BSTEP(2, 0, 0)
        BSTEP(1, 1, 0)
        BSTEP(0, 2, 0)
    }
}

// ---------------- gamma: normalized posteriors + marginal partials ----------------
__global__ void __launch_bounds__(256) gamma_kernel(float* __restrict__ out_probs) {
    int b = blockIdx.x >> 4, chunk = blockIdx.x & 15;
    int w = threadIdx.x >> 5, l = threadIdx.x & 31;
    __shared__ float smarg[8][S_];
    const unsigned FULL = 0xffffffffu;
    float mx = 0.f, my = 0.f;
    int tbase = chunk * 256 + w;
    size_t base = (size_t)b * T_ * S_;
#pragma unroll 4
    for (int k = 0; k < 32; k++) {
        int t = tbase + k * 8;
        size_t idx = base + (size_t)t * S_ + 2 * l;
        float2 va = *(const float2*)&g_alpha[idx];
        float2 vb = *(const float2*)&g_beta[idx];
        float px = va.x * vb.x, py = va.y * vb.y;
        float s = px + py;
#pragma unroll
        for (int off = 16; off; off >>= 1) s += __shfl_xor_sync(FULL, s, off);
        float inv = __fdividef(1.f, s);
        px *= inv; py *= inv;
        *(float2*)&out_probs[idx] = make_float2(px, py);
        mx += px; my += py;
    }
    smarg[w][2 * l] = mx;
    smarg[w][2 * l + 1] = my;
    __syncthreads();
    if (threadIdx.x < S_) {
        float s = 0.f;
#pragma unroll
        for (int ww = 0; ww < 8; ww++) s += smarg[ww][threadIdx.x];
        g_margpart[(size_t)blockIdx.x * S_ + threadIdx.x] = s;
    }
}

__global__ void margreduce_kernel(float* __restrict__ out_marg) {
    int i = blockIdx.x * blockDim.x + threadIdx.x;
    int b = i >> 6, j = i & 63;
    float s = 0.f;
#pragma unroll
    for (int c = 0; c < 16; c++) s += g_margpart[(size_t)(b * 16 + c) * S_ + j];
    out_marg[i] = s * (1.f / (float)T_);
}

// ---------------- launch ----------------
extern "C" void kernel_launch(void* const* d_in, const int* in_sizes, int n_in,
                              void* d_out, int out_size) {
    const float* obs = (const float*)d_in[0];
    const float* W1 = (const float*)d_in[1];
    const float* b1 = (const float*)d_in[2];
    const float* W2 = (const float*)d_in[3];
    const float* b2 = (const float*)d_in[4];
    const float* W3 = (const float*)d_in[5];
    const float* b3 = (const float*)d_in[6];
    const float* ltm = (const float*)d_in[7];
    const float* lip = (const float*)d_in[8];
    const float* lr = (const float*)d_in[9];
    const float* lp = (const float*)d_in[10];

    float* out = (float*)d_out;
    float* out_probs = out;
    float* out_marg = out + (size_t)B_ * T_ * S_;
    float* out_dur = out_marg + (size_t)B_ * S_;
    float* out_ll = out_dur + S_;

    const int smem_bytes = (D_ * H_ + H_ * H_ + H_ * S_ + H_ + H_ + S_ + 4 * 4096) * 4;
    cudaFuncSetAttribute(mlp_kernel, cudaFuncAttributeMaxDynamicSharedMemorySize, smem_bytes);

    setup_kernel<<<1, 64>>>(ltm, lip, lr, lp, out_dur);
    mlp_kernel<<<1024, 128, smem_bytes>>>(obs, W1, b1, W2, b2, W3, b3);
    recursion_kernel<<<16, 128>>>(out_ll);
    gamma_kernel<<<512, 256>>>(out_probs);
    margreduce_kernel<<<8, 256>>>(out_marg);
}